// round 12
// baseline (speedup 1.0000x reference)
#include <cuda_runtime.h>
#include <math.h>

// out = sign(x @ sign(W)) : fp32 GEMM, per-output single-accumulator k-ascending
// RN-FMA chains (bit-identical to the passing R11 kernel). fma.rn.f32x2 packed
// over M-row pairs; TM=16 x TN=4 microtile cuts smem wavefronts/FMA.
// M=8192, K=2048, N=2048.

#define BM 128
#define BN 128
#define BK 16
#define TM 16
#define TN 4
#define NTHREADS 256

__device__ __forceinline__ float sgnf(float v) {
    return (v > 0.0f) ? 1.0f : ((v < 0.0f) ? -1.0f : 0.0f);
}

__device__ __forceinline__ unsigned long long pack_dup(float x) {
    unsigned long long r;
    asm("mov.b64 %0, {%1, %1};" : "=l"(r) : "f"(x));
    return r;
}

__device__ __forceinline__ void fma2(unsigned long long& d,
                                     unsigned long long a,
                                     unsigned long long b) {
    asm("fma.rn.f32x2 %0, %1, %2, %0;" : "+l"(d) : "l"(a), "l"(b));
}

__device__ __forceinline__ float2 unpack2(unsigned long long v) {
    float2 r;
    asm("mov.b64 {%0, %1}, %2;" : "=f"(r.x), "=f"(r.y) : "l"(v));
    return r;
}

__global__ __launch_bounds__(NTHREADS)
void binary_gemm_kernel(const float* __restrict__ X,   // [M, K] row-major
                        const float* __restrict__ W,   // [K, N] row-major
                        float* __restrict__ O,         // [M, N] row-major
                        int M, int N, int K)
{
    __shared__ float As[2][BK][BM];   // transposed A tiles (double buffer)
    __shared__ float Bs[2][BK][BN];   // binarized B tiles  (double buffer)

    const int bx = blockIdx.x;
    const int by = blockIdx.y;
    const int tid = threadIdx.x;
    const int tx = tid & 31;          // 0..31 : N slot (4 cols)
    const int ty = tid >> 5;          // 0..7  : M slot (16 rows)

    const float* Xblk = X + (size_t)by * BM * K;
    const float* Wblk = W + (size_t)bx * BN;

    // acc2[ip][j]: lane0 = row ty*16+2ip, lane1 = row ty*16+2ip+1, col tx*4+j.
    // Each lane is its own k-ascending fp32 RN-FMA chain.
    unsigned long long acc2[TM / 2][TN];
    #pragma unroll
    for (int i = 0; i < TM / 2; i++)
        #pragma unroll
        for (int j = 0; j < TN; j++)
            acc2[i][j] = 0ULL;

    // gmem staging plan (identical tiles/layout to R11):
    const int arow  = tid >> 2;
    const int acol4 = (tid & 3) * 4;
    const int brow  = tid >> 5;
    const int bcol4 = (tid & 31) * 4;

    const float* aptr0 = Xblk + (size_t)arow * K + acol4;
    const float* aptr1 = Xblk + (size_t)(arow + 64) * K + acol4;
    const float* bptr0 = Wblk + (size_t)brow * N + bcol4;
    const float* bptr1 = Wblk + (size_t)(brow + 8) * N + bcol4;

    // ---- prologue: tile 0 -> buffer 0 ----
    {
        float4 va0 = *reinterpret_cast<const float4*>(aptr0);
        float4 va1 = *reinterpret_cast<const float4*>(aptr1);
        float4 vb0 = *reinterpret_cast<const float4*>(bptr0);
        float4 vb1 = *reinterpret_cast<const float4*>(bptr1);
        As[0][acol4 + 0][arow] = va0.x;
        As[0][acol4 + 1][arow] = va0.y;
        As[0][acol4 + 2][arow] = va0.z;
        As[0][acol4 + 3][arow] = va0.w;
        As[0][acol4 + 0][arow + 64] = va1.x;
        As[0][acol4 + 1][arow + 64] = va1.y;
        As[0][acol4 + 2][arow + 64] = va1.z;
        As[0][acol4 + 3][arow + 64] = va1.w;
        float4 s0, s1;
        s0.x = sgnf(vb0.x); s0.y = sgnf(vb0.y); s0.z = sgnf(vb0.z); s0.w = sgnf(vb0.w);
        s1.x = sgnf(vb1.x); s1.y = sgnf(vb1.y); s1.z = sgnf(vb1.z); s1.w = sgnf(vb1.w);
        *reinterpret_cast<float4*>(&Bs[0][brow][bcol4]) = s0;
        *reinterpret_cast<float4*>(&Bs[0][brow + 8][bcol4]) = s1;
    }
    __syncthreads();

    int buf = 0;
    for (int kt = 0; kt < K; kt += BK) {
        const int knext = kt + BK;
        float4 va0, va1, vb0, vb1;
        const bool has_next = (knext < K);
        if (has_next) {
            va0 = *reinterpret_cast<const float4*>(aptr0 + knext);
            va1 = *reinterpret_cast<const float4*>(aptr1 + knext);
            vb0 = *reinterpret_cast<const float4*>(bptr0 + (size_t)knext * N);
            vb1 = *reinterpret_cast<const float4*>(bptr1 + (size_t)knext * N);
        }

        // ---- compute: k ascending; one f32x2 FMA per (row-pair, col, k) ----
        #pragma unroll
        for (int k = 0; k < BK; k++) {
            // A row-pairs, packed straight from smem (broadcast within warp)
            const ulonglong2* ap =
                reinterpret_cast<const ulonglong2*>(&As[buf][k][ty * TM]);
            ulonglong2 q0 = ap[0];
            ulonglong2 q1 = ap[1];
            ulonglong2 q2 = ap[2];
            ulonglong2 q3 = ap[3];
            unsigned long long a2[TM / 2] =
                {q0.x, q0.y, q1.x, q1.y, q2.x, q2.y, q3.x, q3.y};
            // B: 4 cols, duplicated into both lanes
            float4 bv = *reinterpret_cast<const float4*>(&Bs[buf][k][tx * TN]);
            unsigned long long bd[TN] =
                {pack_dup(bv.x), pack_dup(bv.y), pack_dup(bv.z), pack_dup(bv.w)};
            #pragma unroll
            for (int i = 0; i < TM / 2; i++)
                #pragma unroll
                for (int j = 0; j < TN; j++)
                    fma2(acc2[i][j], a2[i], bd[j]);
        }

        if (has_next) {
            const int nb = buf ^ 1;
            As[nb][acol4 + 0][arow] = va0.x;
            As[nb][acol4 + 1][arow] = va0.y;
            As[nb][acol4 + 2][arow] = va0.z;
            As[nb][acol4 + 3][arow] = va0.w;
            As[nb][acol4 + 0][arow + 64] = va1.x;
            As[nb][acol4 + 1][arow + 64] = va1.y;
            As[nb][acol4 + 2][arow + 64] = va1.z;
            As[nb][acol4 + 3][arow + 64] = va1.w;
            float4 s0, s1;
            s0.x = sgnf(vb0.x); s0.y = sgnf(vb0.y); s0.z = sgnf(vb0.z); s0.w = sgnf(vb0.w);
            s1.x = sgnf(vb1.x); s1.y = sgnf(vb1.y); s1.z = sgnf(vb1.z); s1.w = sgnf(vb1.w);
            *reinterpret_cast<float4*>(&Bs[nb][brow][bcol4]) = s0;
            *reinterpret_cast<float4*>(&Bs[nb][brow + 8][bcol4]) = s1;
            __syncthreads();
            buf = nb;
        }
    }

    // ---- epilogue: unpack row-pairs, sign, store float4 per row ----
    float* Oblk = O + (size_t)(by * BM + ty * TM) * N + bx * BN + tx * TN;
    #pragma unroll
    for (int ip = 0; ip < TM / 2; ip++) {
        float2 u0 = unpack2(acc2[ip][0]);
        float2 u1 = unpack2(acc2[ip][1]);
        float2 u2 = unpack2(acc2[ip][2]);
        float2 u3 = unpack2(acc2[ip][3]);
        float4 r0, r1;
        r0.x = sgnf(u0.x); r0.y = sgnf(u1.x); r0.z = sgnf(u2.x); r0.w = sgnf(u3.x);
        r1.x = sgnf(u0.y); r1.y = sgnf(u1.y); r1.z = sgnf(u2.y); r1.w = sgnf(u3.y);
        *reinterpret_cast<float4*>(Oblk + (size_t)(2 * ip) * N) = r0;
        *reinterpret_cast<float4*>(Oblk + (size_t)(2 * ip + 1) * N) = r1;
    }
}

extern "C" void kernel_launch(void* const* d_in, const int* in_sizes, int n_in,
                              void* d_out, int out_size) {
    const float* x = (const float*)d_in[0];      // [M, K]
    const float* w = (const float*)d_in[1];      // [K, N] (square)
    float* out = (float*)d_out;                  // [M, N]

    int K = 1;
    {
        long long kw = in_sizes[1];
        long long r = (long long)(sqrt((double)kw));
        while (r * r < kw) r++;
        while (r * r > kw) r--;
        K = (int)r;
    }
    int N = (int)(in_sizes[1] / K);
    int M = (int)(in_sizes[0] / K);

    dim3 grid(N / BN, M / BM);
    dim3 block(NTHREADS);
    binary_gemm_kernel<<<grid, block>>>(x, w, out, M, N, K);
}

// round 15
// speedup vs baseline: 1.1869x; 1.1869x over previous
#include <cuda_runtime.h>
#include <math.h>

// out = sign(x @ sign(W)) : fp32 GEMM, per-output single-accumulator k-ascending
// RN-FMA chains (bit-identical to passing R11/R12 kernels; rel_err 9.77e-4).
// R13: W pre-binarized in a prepass; B tile staged with cp.async (no regs);
// __launch_bounds__(256,2) to restore 2 CTAs/SM.
// M=8192, K=2048, N=2048.

#define BM 128
#define BN 128
#define BK 16
#define TM 16
#define TN 4
#define NTHREADS 256

#define MAXK 2048
#define MAXN 2048
__device__ float g_WB[(size_t)MAXK * MAXN];   // binarized W, 16 MB

__device__ __forceinline__ float sgnf(float v) {
    return (v > 0.0f) ? 1.0f : ((v < 0.0f) ? -1.0f : 0.0f);
}

__device__ __forceinline__ unsigned long long pack_dup(float x) {
    unsigned long long r;
    asm("mov.b64 %0, {%1, %1};" : "=l"(r) : "f"(x));
    return r;
}

__device__ __forceinline__ void fma2(unsigned long long& d,
                                     unsigned long long a,
                                     unsigned long long b) {
    asm("fma.rn.f32x2 %0, %1, %2, %0;" : "+l"(d) : "l"(a), "l"(b));
}

__device__ __forceinline__ float2 unpack2(unsigned long long v) {
    float2 r;
    asm("mov.b64 {%0, %1}, %2;" : "=f"(r.x), "=f"(r.y) : "l"(v));
    return r;
}

__device__ __forceinline__ void cp_async16(void* smem_dst, const void* gmem_src) {
    unsigned saddr = (unsigned)__cvta_generic_to_shared(smem_dst);
    asm volatile("cp.async.cg.shared.global [%0], [%1], 16;"
                 :: "r"(saddr), "l"(gmem_src));
}
__device__ __forceinline__ void cp_async_commit() {
    asm volatile("cp.async.commit_group;");
}
__device__ __forceinline__ void cp_async_wait0() {
    asm volatile("cp.async.wait_group 0;");
}

// ---- prepass: binarize W -> g_WB ----
__global__ void sign_w_kernel(const float* __restrict__ W, size_t n) {
    size_t i = ((size_t)blockIdx.x * blockDim.x + threadIdx.x) * 4;
    if (i + 3 < n) {
        float4 v = *reinterpret_cast<const float4*>(W + i);
        float4 s;
        s.x = sgnf(v.x); s.y = sgnf(v.y); s.z = sgnf(v.z); s.w = sgnf(v.w);
        *reinterpret_cast<float4*>(g_WB + i) = s;
    } else {
        for (; i < n; i++) g_WB[i] = sgnf(W[i]);
    }
}

__global__ __launch_bounds__(NTHREADS, 2)
void binary_gemm_kernel(const float* __restrict__ X,   // [M, K] row-major
                        float* __restrict__ O,         // [M, N] row-major
                        int M, int N, int K)
{
    __shared__ float As[2][BK][BM];   // transposed A tiles (double buffer)
    __shared__ float Bs[2][BK][BN];   // binarized B tiles  (double buffer)

    const int bx = blockIdx.x;
    const int by = blockIdx.y;
    const int tid = threadIdx.x;
    const int tx = tid & 31;          // N slot (4 cols)
    const int ty = tid >> 5;          // M slot (16 rows)

    const float* Xblk = X + (size_t)by * BM * K;
    const float* WBblk = g_WB + (size_t)bx * BN;

    // acc2[ip][j]: lane0 = row ty*16+2ip, lane1 = row +1, col tx*4+j.
    unsigned long long acc2[TM / 2][TN];
    #pragma unroll
    for (int i = 0; i < TM / 2; i++)
        #pragma unroll
        for (int j = 0; j < TN; j++)
            acc2[i][j] = 0ULL;

    // A staging (register prefetch, transpose into As[k][m]):
    const int arow  = tid >> 2;
    const int acol4 = (tid & 3) * 4;
    const float* aptr0 = Xblk + (size_t)arow * K + acol4;
    const float* aptr1 = Xblk + (size_t)(arow + 64) * K + acol4;

    // B staging (cp.async, 2 x 16B per thread): chunk c = tid + t*256,
    // row = c>>5 (0..15), col4 = (c&31)*4.
    const int brow0 = tid >> 5;            // rows 0..7
    const int brow1 = (tid + 256) >> 5;    // rows 8..15
    const int bcol4 = (tid & 31) * 4;
    const float* bsrc0 = WBblk + (size_t)brow0 * N + bcol4;
    const float* bsrc1 = WBblk + (size_t)brow1 * N + bcol4;

    // ---- prologue: tile 0 -> buffer 0 ----
    cp_async16(&Bs[0][brow0][bcol4], bsrc0);
    cp_async16(&Bs[0][brow1][bcol4], bsrc1);
    cp_async_commit();
    {
        float4 va0 = *reinterpret_cast<const float4*>(aptr0);
        float4 va1 = *reinterpret_cast<const float4*>(aptr1);
        As[0][acol4 + 0][arow] = va0.x;
        As[0][acol4 + 1][arow] = va0.y;
        As[0][acol4 + 2][arow] = va0.z;
        As[0][acol4 + 3][arow] = va0.w;
        As[0][acol4 + 0][arow + 64] = va1.x;
        As[0][acol4 + 1][arow + 64] = va1.y;
        As[0][acol4 + 2][arow + 64] = va1.z;
        As[0][acol4 + 3][arow + 64] = va1.w;
    }
    cp_async_wait0();
    __syncthreads();

    int buf = 0;
    for (int kt = 0; kt < K; kt += BK) {
        const int knext = kt + BK;
        const bool has_next = (knext < K);
        const int nb = buf ^ 1;
        float4 va0, va1;
        if (has_next) {
            // B(next): async into nb (nb's old tile retired at last sync)
            cp_async16(&Bs[nb][brow0][bcol4], bsrc0 + (size_t)knext * N);
            cp_async16(&Bs[nb][brow1][bcol4], bsrc1 + (size_t)knext * N);
            cp_async_commit();
            // A(next): register prefetch (overlaps compute)
            va0 = *reinterpret_cast<const float4*>(aptr0 + knext);
            va1 = *reinterpret_cast<const float4*>(aptr1 + knext);
        }

        // ---- compute: k ascending; one f32x2 FMA per (row-pair, col, k) ----
        #pragma unroll
        for (int k = 0; k < BK; k++) {
            const ulonglong2* ap =
                reinterpret_cast<const ulonglong2*>(&As[buf][k][ty * TM]);
            ulonglong2 q0 = ap[0];
            ulonglong2 q1 = ap[1];
            ulonglong2 q2 = ap[2];
            ulonglong2 q3 = ap[3];
            unsigned long long a2[TM / 2] =
                {q0.x, q0.y, q1.x, q1.y, q2.x, q2.y, q3.x, q3.y};
            float4 bv = *reinterpret_cast<const float4*>(&Bs[buf][k][tx * TN]);
            unsigned long long bd[TN] =
                {pack_dup(bv.x), pack_dup(bv.y), pack_dup(bv.z), pack_dup(bv.w)};
            #pragma unroll
            for (int i = 0; i < TM / 2; i++)
                #pragma unroll
                for (int j = 0; j < TN; j++)
                    fma2(acc2[i][j], a2[i], bd[j]);
        }

        if (has_next) {
            As[nb][acol4 + 0][arow] = va0.x;
            As[nb][acol4 + 1][arow] = va0.y;
            As[nb][acol4 + 2][arow] = va0.z;
            As[nb][acol4 + 3][arow] = va0.w;
            As[nb][acol4 + 0][arow + 64] = va1.x;
            As[nb][acol4 + 1][arow + 64] = va1.y;
            As[nb][acol4 + 2][arow + 64] = va1.z;
            As[nb][acol4 + 3][arow + 64] = va1.w;
            cp_async_wait0();
            __syncthreads();
            buf = nb;
        }
    }

    // ---- epilogue: unpack row-pairs, sign, store float4 per row ----
    float* Oblk = O + (size_t)(by * BM + ty * TM) * N + bx * BN + tx * TN;
    #pragma unroll
    for (int ip = 0; ip < TM / 2; ip++) {
        float2 u0 = unpack2(acc2[ip][0]);
        float2 u1 = unpack2(acc2[ip][1]);
        float2 u2 = unpack2(acc2[ip][2]);
        float2 u3 = unpack2(acc2[ip][3]);
        float4 r0, r1;
        r0.x = sgnf(u0.x); r0.y = sgnf(u1.x); r0.z = sgnf(u2.x); r0.w = sgnf(u3.x);
        r1.x = sgnf(u0.y); r1.y = sgnf(u1.y); r1.z = sgnf(u2.y); r1.w = sgnf(u3.y);
        *reinterpret_cast<float4*>(Oblk + (size_t)(2 * ip) * N) = r0;
        *reinterpret_cast<float4*>(Oblk + (size_t)(2 * ip + 1) * N) = r1;
    }
}

extern "C" void kernel_launch(void* const* d_in, const int* in_sizes, int n_in,
                              void* d_out, int out_size) {
    const float* x = (const float*)d_in[0];      // [M, K]
    const float* w = (const float*)d_in[1];      // [K, N] (square)
    float* out = (float*)d_out;                  // [M, N]

    int K = 1;
    {
        long long kw = in_sizes[1];
        long long r = (long long)(sqrt((double)kw));
        while (r * r < kw) r++;
        while (r * r > kw) r--;
        K = (int)r;
    }
    int N = (int)(in_sizes[1] / K);
    int M = (int)(in_sizes[0] / K);

    size_t nw = (size_t)K * N;
    sign_w_kernel<<<(unsigned)((nw / 4 + 255) / 256), 256>>>(w, nw);

    dim3 grid(N / BN, M / BM);
    dim3 block(NTHREADS);
    binary_gemm_kernel<<<grid, block>>>(x, out, M, N, K);
}